// round 8
// baseline (speedup 1.0000x reference)
#include <cuda_runtime.h>
#include <cuda_fp16.h>
#include <math.h>
#include <stdint.h>

#define N_TOK 32768
#define F_IN  512
#define F_HID 2048
#define F_OUT 512

// ---------------- scratch (static device globals; no runtime alloc) ----------
__device__ float g_Y1[F_IN * F_HID];               // solve(M1^T, W1^T): [512][2048]
__device__ float g_Y2[F_HID * F_OUT];              // [2048][512]
__device__ __half g_W1[F_HID * F_IN];              // folded W1 fp16 [2048][512]
__device__ __half g_W2[F_OUT * F_HID];             // folded W2 fp16 [512][2048]
__device__ __half g_x16[(size_t)N_TOK * F_IN];     // x fp16   32 MB
__device__ __half g_h16[(size_t)N_TOK * F_HID];    // h fp16  128 MB

// ======================= helpers =======================
__device__ __forceinline__ uint32_t smem_u32(const void* p) {
    uint32_t a;
    asm("{ .reg .u64 t; cvta.to.shared.u64 t, %1; cvt.u32.u64 %0, t; }"
        : "=r"(a) : "l"(p));
    return a;
}
__device__ __forceinline__ void cp16(uint32_t dst, const void* src) {
    asm volatile("cp.async.cg.shared.global [%0], [%1], 16;" :: "r"(dst), "l"(src));
}
__device__ __forceinline__ void cp_commit() {
    asm volatile("cp.async.commit_group;" ::: "memory");
}
template <int NN> __device__ __forceinline__ void cp_wait() {
    asm volatile("cp.async.wait_group %0;" :: "n"(NN) : "memory");
}
__device__ __forceinline__ void ldm_x4(uint32_t& r0, uint32_t& r1, uint32_t& r2,
                                       uint32_t& r3, uint32_t a) {
    asm volatile("ldmatrix.sync.aligned.m8n8.x4.shared.b16 {%0,%1,%2,%3}, [%4];"
        : "=r"(r0), "=r"(r1), "=r"(r2), "=r"(r3) : "r"(a));
}
__device__ __forceinline__ void mma_f16(float* c, const uint32_t* a,
                                        uint32_t b0, uint32_t b1) {
    asm volatile("mma.sync.aligned.m16n8k16.row.col.f32.f16.f16.f32 "
        "{%0,%1,%2,%3}, {%4,%5,%6,%7}, {%8,%9}, {%0,%1,%2,%3};"
        : "+f"(c[0]), "+f"(c[1]), "+f"(c[2]), "+f"(c[3])
        : "r"(a[0]), "r"(a[1]), "r"(a[2]), "r"(a[3]), "r"(b0), "r"(b1));
}
__device__ __forceinline__ uint32_t packh(__half a, __half b) {
    return (uint32_t)__half_as_ushort(a) | ((uint32_t)__half_as_ushort(b) << 16);
}

// ======================= fused factorize + solve =======================
// Each block recomputes the Thomas factorization of M^T in smem, then solves
// 128 RHS columns. Blocks 0..15: layer 1 (n=512); blocks 16..19: layer 2 (n=2048).
__global__ void __launch_bounds__(128) solve_both(
    const float* d1, const float* l1, const float* u1, const float* W1, float* Y1,
    const float* d2, const float* l2, const float* u2, const float* W2, float* Y2) {
    __shared__ float sd[2048], slo[2048], sup[2048];
    int bid = blockIdx.x, t = threadIdx.x;
    const float *d, *l, *u, *W; float* Y; int n, nrhs, j0;
    if (bid < 16) { d = d1; l = l1; u = u1; W = W1; Y = Y1;
                    n = F_IN;  nrhs = F_HID; j0 = bid * 128; }
    else          { d = d2; l = l2; u = u2; W = W2; Y = Y2;
                    n = F_HID; nrhs = F_OUT; j0 = (bid - 16) * 128; }
    for (int i = t; i < n; i += 128) {
        float di = d[i];
        float sp = (di > 20.f) ? di : log1pf(expf(di));
        sd[i]  = sp + 2.f;
        slo[i] = (i > 0)     ? tanhf(u[i - 1]) : 0.f;   // sub of M^T
        sup[i] = (i < n - 1) ? tanhf(l[i])     : 0.f;   // super of M^T
    }
    __syncthreads();
    if (t == 0) {
        float cprev = 0.f;
        for (int i = 0; i < n; i++) {
            float r = __fdividef(1.f, sd[i] - slo[i] * cprev);
            sd[i] = r;                 // reciprocal denominators
            cprev = sup[i] * r;
            sup[i] = cprev;            // modified upper
        }
    }
    __syncthreads();

    int j = j0 + t;
    const float* r = W + (size_t)j * n;
    float z = r[0] * sd[0];
    Y[j] = z;
#pragma unroll 4
    for (int i = 1; i < n; i++) {
        z = (r[i] - slo[i] * z) * sd[i];
        Y[(size_t)i * nrhs + j] = z;
    }
    float y = z;
#pragma unroll 4
    for (int i = n - 2; i >= 0; i--) {
        y = Y[(size_t)i * nrhs + j] - sup[i] * y;
        Y[(size_t)i * nrhs + j] = y;
    }
}

// transpose [R][C] fp32 -> [C][R] fp16
__global__ void trans_f16(const float* __restrict__ in, __half* __restrict__ out,
                          int R, int C) {
    __shared__ float t[32][33];
    int c0 = blockIdx.x * 32, r0 = blockIdx.y * 32;
    int x = threadIdx.x, y = threadIdx.y;
#pragma unroll
    for (int i = 0; i < 32; i += 8)
        t[y + i][x] = in[(size_t)(r0 + y + i) * C + c0 + x];
    __syncthreads();
#pragma unroll
    for (int i = 0; i < 32; i += 8)
        out[(size_t)(c0 + y + i) * R + r0 + x] = __float2half_rn(t[x][y + i]);
}

// cast x fp32 -> fp16
__global__ void cast_f16(const float4* __restrict__ x, uint2* __restrict__ o, int n4) {
    int i = blockIdx.x * blockDim.x + threadIdx.x;
    if (i >= n4) return;
    float4 v = x[i];
    o[i] = make_uint2(packh(__float2half_rn(v.x), __float2half_rn(v.y)),
                      packh(__float2half_rn(v.z), __float2half_rn(v.w)));
}

// ======================= fp16 mma.sync GEMM =======================
// C[M,N] = A[M,K] @ B[N,K]^T (+bias)(+relu).  fp16 in, fp32 accum.
// CTA tile 128 x (PT*32), 8 warps (wm 0..3 x wn 0..1), warp tile 32 x (PT*16).
// BK=32, 4 stages, 2 CTAs/SM, single __syncthreads per stage.
#define GSTAGES 4
#define TILE_A  8192u                   // 128x32 fp16

// swizzled byte offset inside a (rows x 32) fp16 tile (64B rows, 4x16B segs)
__device__ __forceinline__ uint32_t swz(int r, int sg) {
    return (uint32_t)(r * 64 + ((sg ^ ((r >> 1) & 3)) << 4));
}

template <int PT>
__device__ __forceinline__ void load_stage(uint32_t sbase, int buf,
    const __half* A, const __half* B,
    int rowB, int colB, int K, int off, int tid) {
    constexpr int CN = PT * 32;                       // CTA N tile
    constexpr uint32_t STG = TILE_A + (uint32_t)CN * 64u;
    constexpr int CHUNKS = (512 + CN * 4) / 256;      // 16B chunks per thread
    uint32_t s0 = sbase + (uint32_t)buf * STG;
#pragma unroll
    for (int i = 0; i < CHUNKS; i++) {
        int flat = tid + i * 256;
        if (flat < 512) {
            int r = flat >> 2, sg = flat & 3;
            cp16(s0 + swz(r, sg), A + (size_t)(rowB + r) * K + off + sg * 8);
        } else {
            int f2 = flat - 512;
            int r = f2 >> 2, sg = f2 & 3;
            cp16(s0 + TILE_A + swz(r, sg), B + (size_t)(colB + r) * K + off + sg * 8);
        }
    }
    cp_commit();
}

template <int PT, bool FUSE>   // FUSE: relu + fp16 out (Ch); else fp32 out (Cf)
__global__ void __launch_bounds__(256, 2) gemm_f16(
    const __half* __restrict__ A, const __half* __restrict__ B,
    const float* __restrict__ bias, float* __restrict__ Cf,
    __half* __restrict__ Ch, int N, int K) {
    constexpr int CN = PT * 32;
    constexpr uint32_t STG = TILE_A + (uint32_t)CN * 64u;
    extern __shared__ char smem[];
    uint32_t sb = smem_u32(smem);
    const int tid = threadIdx.x;
    const int lane = tid & 31, wid = tid >> 5;
    const int wm = wid & 3, wn = wid >> 2;       // warp tile 32(m) x PT*16(n)
    const int rowB = blockIdx.y * 128, colB = blockIdx.x * CN;
    const int per = K >> 5;

    float acc[2][2 * PT][4] = {};

#pragma unroll
    for (int s = 0; s < GSTAGES - 1; s++)
        load_stage<PT>(sb, s, A, B, rowB, colB, K, s << 5, tid);

    const int lr = lane & 15, kh = lane >> 4;
    const int lg = lane >> 2, lt = lane & 3;

    for (int s = 0; s < per; s++) {
        cp_wait<GSTAGES - 2>();
        __syncthreads();

        int pf = s + GSTAGES - 1;
        if (pf < per)
            load_stage<PT>(sb, pf % GSTAGES, A, B, rowB, colB, K, pf << 5, tid);
        else
            cp_commit();

        uint32_t sA = sb + (uint32_t)(s % GSTAGES) * STG;
        uint32_t sBs = sA + TILE_A;
#pragma unroll
        for (int kk = 0; kk < 2; kk++) {
            uint32_t a[2][4];
#pragma unroll
            for (int mt = 0; mt < 2; mt++) {
                int r = wm * 32 + mt * 16 + lr;
                ldm_x4(a[mt][0], a[mt][1], a[mt][2], a[mt][3],
                       sA + swz(r, 2 * kk + kh));
            }
#pragma unroll
            for (int pt = 0; pt < PT; pt++) {
                int r = wn * (PT * 16) + pt * 16 + lr;
                uint32_t b0, b1, b2, b3;
                ldm_x4(b0, b1, b2, b3, sBs + swz(r, 2 * kk + kh));
#pragma unroll
                for (int mt = 0; mt < 2; mt++) {
                    mma_f16(acc[mt][2 * pt],     a[mt], b0, b2);
                    mma_f16(acc[mt][2 * pt + 1], a[mt], b1, b3);
                }
            }
        }
        // single sync per stage: the top-of-loop barrier at s+1 protects
        // buffer (s)%4 before it is overwritten at s+4.
    }

    // epilogue
#pragma unroll
    for (int mt = 0; mt < 2; mt++) {
        int r0 = rowB + wm * 32 + mt * 16 + lg;
#pragma unroll
        for (int n8 = 0; n8 < 2 * PT; n8++) {
            int c = colB + wn * (PT * 16) + n8 * 8 + 2 * lt;
            float b0v = bias[c], b1v = bias[c + 1];
            float v0 = acc[mt][n8][0] + b0v;
            float v1 = acc[mt][n8][1] + b1v;
            float v2 = acc[mt][n8][2] + b0v;
            float v3 = acc[mt][n8][3] + b1v;
            if (FUSE) {
                v0 = fmaxf(v0, 0.f); v1 = fmaxf(v1, 0.f);
                v2 = fmaxf(v2, 0.f); v3 = fmaxf(v3, 0.f);
                *(uint32_t*)(Ch + (size_t)r0 * N + c) =
                    packh(__float2half_rn(v0), __float2half_rn(v1));
                *(uint32_t*)(Ch + (size_t)(r0 + 8) * N + c) =
                    packh(__float2half_rn(v2), __float2half_rn(v3));
            } else {
                *(float2*)(Cf + (size_t)r0 * N + c)       = make_float2(v0, v1);
                *(float2*)(Cf + (size_t)(r0 + 8) * N + c) = make_float2(v2, v3);
            }
        }
    }
}

#define SMEM_G1 (GSTAGES * (TILE_A + 128u * 64u))   // PT=4: 64 KB
#define SMEM_G2 (GSTAGES * (TILE_A + 64u * 64u))    // PT=2: 48 KB

// ======================= launch =======================
extern "C" void kernel_launch(void* const* d_in, const int* in_sizes, int n_in,
                              void* d_out, int out_size) {
    const float* x  = (const float*)d_in[0];
    const float* d1 = (const float*)d_in[1];
    const float* l1 = (const float*)d_in[2];
    const float* u1 = (const float*)d_in[3];
    const float* W1 = (const float*)d_in[4];
    const float* b1 = (const float*)d_in[5];
    const float* d2 = (const float*)d_in[6];
    const float* l2 = (const float*)d_in[7];
    const float* u2 = (const float*)d_in[8];
    const float* W2 = (const float*)d_in[9];
    const float* b2 = (const float*)d_in[10];
    float* out = (float*)d_out;

    float *Y1, *Y2;
    __half *W1f, *W2f, *x16, *h16;
    cudaGetSymbolAddress((void**)&Y1,  g_Y1);
    cudaGetSymbolAddress((void**)&Y2,  g_Y2);
    cudaGetSymbolAddress((void**)&W1f, g_W1);
    cudaGetSymbolAddress((void**)&W2f, g_W2);
    cudaGetSymbolAddress((void**)&x16, g_x16);
    cudaGetSymbolAddress((void**)&h16, g_h16);

    cudaFuncSetAttribute((const void*)gemm_f16<4, true>,
                         cudaFuncAttributeMaxDynamicSharedMemorySize, SMEM_G1);
    cudaFuncSetAttribute((const void*)gemm_f16<2, false>,
                         cudaFuncAttributeMaxDynamicSharedMemorySize, SMEM_G2);

    // 1) factorize (per-block, smem) + fold tridiag solves into weights
    solve_both<<<20, 128>>>(d1, l1, u1, W1, Y1, d2, l2, u2, W2, Y2);
    // 2) transpose folded weights to row-major fp16
    trans_f16<<<dim3(F_HID / 32, F_IN / 32),  dim3(32, 8)>>>(Y1, W1f, F_IN,  F_HID);
    trans_f16<<<dim3(F_OUT / 32, F_HID / 32), dim3(32, 8)>>>(Y2, W2f, F_HID, F_OUT);
    // 3) cast x to fp16
    {
        int n4 = (N_TOK * F_IN) / 4;
        cast_f16<<<(n4 + 255) / 256, 256>>>((const float4*)x, (uint2*)x16, n4);
    }
    // 4) h = relu(x @ W1p^T + b1) -> fp16   (tile 128x128)
    gemm_f16<4, true><<<dim3(F_HID / 128, N_TOK / 128), 256, SMEM_G1>>>(
        x16, W1f, b1, nullptr, h16, F_HID, F_IN);
    // 5) out = h @ W2p^T + b2 -> fp32       (tile 128x64, wave-friendly)
    gemm_f16<2, false><<<dim3(F_OUT / 64, N_TOK / 128), 256, SMEM_G2>>>(
        h16, W2f, b2, out, nullptr, F_OUT, F_HID);
}

// round 9
// speedup vs baseline: 1.0075x; 1.0075x over previous
#include <cuda_runtime.h>
#include <cuda_fp16.h>
#include <math.h>
#include <stdint.h>

#define N_TOK 32768
#define F_IN  512
#define F_HID 2048
#define F_OUT 512

// ---------------- scratch (static device globals; no runtime alloc) ----------
__device__ float g_Y1[F_IN * F_HID];               // solve(M1^T, W1^T): [512][2048]
__device__ float g_Y2[F_HID * F_OUT];              // [2048][512]
__device__ __half g_W1[F_HID * F_IN];              // folded W1 fp16 [2048][512]
__device__ __half g_W2[F_OUT * F_HID];             // folded W2 fp16 [512][2048]
__device__ __half g_x16[(size_t)N_TOK * F_IN];     // x fp16   32 MB
__device__ __half g_h16[(size_t)N_TOK * F_HID];    // h fp16  128 MB

// ======================= helpers =======================
__device__ __forceinline__ uint32_t smem_u32(const void* p) {
    uint32_t a;
    asm("{ .reg .u64 t; cvta.to.shared.u64 t, %1; cvt.u32.u64 %0, t; }"
        : "=r"(a) : "l"(p));
    return a;
}
__device__ __forceinline__ void cp16(uint32_t dst, const void* src) {
    asm volatile("cp.async.cg.shared.global [%0], [%1], 16;" :: "r"(dst), "l"(src));
}
__device__ __forceinline__ void cp_commit() {
    asm volatile("cp.async.commit_group;" ::: "memory");
}
template <int NN> __device__ __forceinline__ void cp_wait() {
    asm volatile("cp.async.wait_group %0;" :: "n"(NN) : "memory");
}
__device__ __forceinline__ void ldm_x4(uint32_t& r0, uint32_t& r1, uint32_t& r2,
                                       uint32_t& r3, uint32_t a) {
    asm volatile("ldmatrix.sync.aligned.m8n8.x4.shared.b16 {%0,%1,%2,%3}, [%4];"
        : "=r"(r0), "=r"(r1), "=r"(r2), "=r"(r3) : "r"(a));
}
__device__ __forceinline__ void mma_f16(float* c, const uint32_t* a,
                                        uint32_t b0, uint32_t b1) {
    asm volatile("mma.sync.aligned.m16n8k16.row.col.f32.f16.f16.f32 "
        "{%0,%1,%2,%3}, {%4,%5,%6,%7}, {%8,%9}, {%0,%1,%2,%3};"
        : "+f"(c[0]), "+f"(c[1]), "+f"(c[2]), "+f"(c[3])
        : "r"(a[0]), "r"(a[1]), "r"(a[2]), "r"(a[3]), "r"(b0), "r"(b1));
}
__device__ __forceinline__ uint32_t packh(__half a, __half b) {
    return (uint32_t)__half_as_ushort(a) | ((uint32_t)__half_as_ushort(b) << 16);
}

// ======================= fused factorize + solve =======================
__global__ void __launch_bounds__(128) solve_both(
    const float* d1, const float* l1, const float* u1, const float* W1, float* Y1,
    const float* d2, const float* l2, const float* u2, const float* W2, float* Y2) {
    __shared__ float sd[2048], slo[2048], sup[2048];
    int bid = blockIdx.x, t = threadIdx.x;
    const float *d, *l, *u, *W; float* Y; int n, nrhs, j0;
    if (bid < 16) { d = d1; l = l1; u = u1; W = W1; Y = Y1;
                    n = F_IN;  nrhs = F_HID; j0 = bid * 128; }
    else          { d = d2; l = l2; u = u2; W = W2; Y = Y2;
                    n = F_HID; nrhs = F_OUT; j0 = (bid - 16) * 128; }
    for (int i = t; i < n; i += 128) {
        float di = d[i];
        float sp = (di > 20.f) ? di : log1pf(expf(di));
        sd[i]  = sp + 2.f;
        slo[i] = (i > 0)     ? tanhf(u[i - 1]) : 0.f;   // sub of M^T
        sup[i] = (i < n - 1) ? tanhf(l[i])     : 0.f;   // super of M^T
    }
    __syncthreads();
    if (t == 0) {
        float cprev = 0.f;
        for (int i = 0; i < n; i++) {
            float r = __fdividef(1.f, sd[i] - slo[i] * cprev);
            sd[i] = r;
            cprev = sup[i] * r;
            sup[i] = cprev;
        }
    }
    __syncthreads();

    int j = j0 + t;
    const float* r = W + (size_t)j * n;
    float z = r[0] * sd[0];
    Y[j] = z;
#pragma unroll 4
    for (int i = 1; i < n; i++) {
        z = (r[i] - slo[i] * z) * sd[i];
        Y[(size_t)i * nrhs + j] = z;
    }
    float y = z;
#pragma unroll 4
    for (int i = n - 2; i >= 0; i--) {
        y = Y[(size_t)i * nrhs + j] - sup[i] * y;
        Y[(size_t)i * nrhs + j] = y;
    }
}

// transpose [R][C] fp32 -> [C][R] fp16
__global__ void trans_f16(const float* __restrict__ in, __half* __restrict__ out,
                          int R, int C) {
    __shared__ float t[32][33];
    int c0 = blockIdx.x * 32, r0 = blockIdx.y * 32;
    int x = threadIdx.x, y = threadIdx.y;
#pragma unroll
    for (int i = 0; i < 32; i += 8)
        t[y + i][x] = in[(size_t)(r0 + y + i) * C + c0 + x];
    __syncthreads();
#pragma unroll
    for (int i = 0; i < 32; i += 8)
        out[(size_t)(c0 + y + i) * R + r0 + x] = __float2half_rn(t[x][y + i]);
}

// cast x fp32 -> fp16
__global__ void cast_f16(const float4* __restrict__ x, uint2* __restrict__ o, int n4) {
    int i = blockIdx.x * blockDim.x + threadIdx.x;
    if (i >= n4) return;
    float4 v = x[i];
    o[i] = make_uint2(packh(__float2half_rn(v.x), __float2half_rn(v.y)),
                      packh(__float2half_rn(v.z), __float2half_rn(v.w)));
}

// ======================= fp16 mma.sync GEMM =======================
// C[M,N] = A[M,K] @ B[N,K]^T (+bias)(+relu). fp16 in, fp32 accum.
// CTA 128x128, 8 warps (32m x 64n warp tile), BK=32 per stage, 6 buffers,
// TWO stages consumed per __syncthreads (64 HMMA/warp between barriers).
#define NBUF 6
#define TILE_A  8192u                   // 128x32 fp16
#define STG_BYTES (2u * TILE_A)         // A + B = 16 KB / stage
#define GEMM_SMEM (NBUF * STG_BYTES)    // 96 KB

// swizzled byte offset inside a 128x32 fp16 tile (64B rows, 4x16B segs)
__device__ __forceinline__ uint32_t swz(int r, int sg) {
    return (uint32_t)(r * 64 + ((sg ^ ((r >> 1) & 3)) << 4));
}

__device__ __forceinline__ void load_stage(uint32_t sbase, int buf,
    const __half* A, const __half* B,
    int rowB, int colB, int K, int off, int tid) {
    uint32_t s0 = sbase + (uint32_t)buf * STG_BYTES;
#pragma unroll
    for (int i = 0; i < 2; i++) {
        int flat = tid + i * 256;          // 0..511
        int r = flat >> 2, sg = flat & 3;
        uint32_t sw = swz(r, sg);
        cp16(s0 + sw,          A + (size_t)(rowB + r) * K + off + sg * 8);
        cp16(s0 + TILE_A + sw, B + (size_t)(colB + r) * K + off + sg * 8);
    }
    cp_commit();
}

__device__ __forceinline__ void consume_stage(uint32_t sA, float acc[2][8][4],
    int wm, int wn, int lr, int kh) {
    uint32_t sBs = sA + TILE_A;
#pragma unroll
    for (int kk = 0; kk < 2; kk++) {
        uint32_t a[2][4];
#pragma unroll
        for (int mt = 0; mt < 2; mt++) {
            int r = wm * 32 + mt * 16 + lr;
            ldm_x4(a[mt][0], a[mt][1], a[mt][2], a[mt][3],
                   sA + swz(r, 2 * kk + kh));
        }
#pragma unroll
        for (int pt = 0; pt < 4; pt++) {
            int r = wn * 64 + pt * 16 + lr;
            uint32_t b0, b1, b2, b3;
            ldm_x4(b0, b1, b2, b3, sBs + swz(r, 2 * kk + kh));
#pragma unroll
            for (int mt = 0; mt < 2; mt++) {
                mma_f16(acc[mt][2 * pt],     a[mt], b0, b2);
                mma_f16(acc[mt][2 * pt + 1], a[mt], b1, b3);
            }
        }
    }
}

template <bool FUSE>   // FUSE: relu + fp16 out (Ch); else fp32 out (Cf)
__global__ void __launch_bounds__(256, 2) gemm_f16(
    const __half* __restrict__ A, const __half* __restrict__ B,
    const float* __restrict__ bias, float* __restrict__ Cf,
    __half* __restrict__ Ch, int N, int K) {
    extern __shared__ char smem[];
    uint32_t sb = smem_u32(smem);
    const int tid = threadIdx.x;
    const int lane = tid & 31, wid = tid >> 5;
    const int wm = wid & 3, wn = wid >> 2;       // warp tile 32(m) x 64(n)
    const int rowB = blockIdx.y * 128, colB = blockIdx.x * 128;
    const int per = K >> 5;                      // 32-K stages (even)
    const int iters = per >> 1;                  // 2 stages per iteration

    float acc[2][8][4] = {};

    // prologue: stages 0..3 into buffers 0..3 (4 commit groups)
#pragma unroll
    for (int s = 0; s < 4; s++)
        load_stage(sb, s, A, B, rowB, colB, K, s << 5, tid);

    const int lr = lane & 15, kh = lane >> 4;
    const int lg = lane >> 2, lt = lane & 3;

    for (int it = 0; it < iters; it++) {
        cp_wait<2>();                 // stages 2*it, 2*it+1 resident
        __syncthreads();

        int pf = 2 * it + 4;
        if (pf < per) {
            int pb = ((it + 2) % 3) * 2;
            load_stage(sb, pb,     A, B, rowB, colB, K, pf << 5, tid);
            load_stage(sb, pb + 1, A, B, rowB, colB, K, (pf + 1) << 5, tid);
        } else {
            cp_commit(); cp_commit();  // keep group accounting
        }

        uint32_t s0 = sb + (uint32_t)((it % 3) * 2) * STG_BYTES;
        consume_stage(s0,             acc, wm, wn, lr, kh);
        consume_stage(s0 + STG_BYTES, acc, wm, wn, lr, kh);
        // buffer pair (it%3) is overwritten only by the prefetch at it+1,
        // which runs after the top-of-loop barrier -> single sync per 2 stages.
    }

    // epilogue
#pragma unroll
    for (int mt = 0; mt < 2; mt++) {
        int r0 = rowB + wm * 32 + mt * 16 + lg;
#pragma unroll
        for (int n8 = 0; n8 < 8; n8++) {
            int c = colB + wn * 64 + n8 * 8 + 2 * lt;
            float b0v = bias[c], b1v = bias[c + 1];
            float v0 = acc[mt][n8][0] + b0v;
            float v1 = acc[mt][n8][1] + b1v;
            float v2 = acc[mt][n8][2] + b0v;
            float v3 = acc[mt][n8][3] + b1v;
            if (FUSE) {
                v0 = fmaxf(v0, 0.f); v1 = fmaxf(v1, 0.f);
                v2 = fmaxf(v2, 0.f); v3 = fmaxf(v3, 0.f);
                *(uint32_t*)(Ch + (size_t)r0 * N + c) =
                    packh(__float2half_rn(v0), __float2half_rn(v1));
                *(uint32_t*)(Ch + (size_t)(r0 + 8) * N + c) =
                    packh(__float2half_rn(v2), __float2half_rn(v3));
            } else {
                *(float2*)(Cf + (size_t)r0 * N + c)       = make_float2(v0, v1);
                *(float2*)(Cf + (size_t)(r0 + 8) * N + c) = make_float2(v2, v3);
            }
        }
    }
}

// ======================= launch =======================
extern "C" void kernel_launch(void* const* d_in, const int* in_sizes, int n_in,
                              void* d_out, int out_size) {
    const float* x  = (const float*)d_in[0];
    const float* d1 = (const float*)d_in[1];
    const float* l1 = (const float*)d_in[2];
    const float* u1 = (const float*)d_in[3];
    const float* W1 = (const float*)d_in[4];
    const float* b1 = (const float*)d_in[5];
    const float* d2 = (const float*)d_in[6];
    const float* l2 = (const float*)d_in[7];
    const float* u2 = (const float*)d_in[8];
    const float* W2 = (const float*)d_in[9];
    const float* b2 = (const float*)d_in[10];
    float* out = (float*)d_out;

    float *Y1, *Y2;
    __half *W1f, *W2f, *x16, *h16;
    cudaGetSymbolAddress((void**)&Y1,  g_Y1);
    cudaGetSymbolAddress((void**)&Y2,  g_Y2);
    cudaGetSymbolAddress((void**)&W1f, g_W1);
    cudaGetSymbolAddress((void**)&W2f, g_W2);
    cudaGetSymbolAddress((void**)&x16, g_x16);
    cudaGetSymbolAddress((void**)&h16, g_h16);

    cudaFuncSetAttribute((const void*)gemm_f16<true>,
                         cudaFuncAttributeMaxDynamicSharedMemorySize, GEMM_SMEM);
    cudaFuncSetAttribute((const void*)gemm_f16<false>,
                         cudaFuncAttributeMaxDynamicSharedMemorySize, GEMM_SMEM);

    // 1) factorize (per-block, smem) + fold tridiag solves into weights
    solve_both<<<20, 128>>>(d1, l1, u1, W1, Y1, d2, l2, u2, W2, Y2);
    // 2) transpose folded weights to row-major fp16
    trans_f16<<<dim3(F_HID / 32, F_IN / 32),  dim3(32, 8)>>>(Y1, W1f, F_IN,  F_HID);
    trans_f16<<<dim3(F_OUT / 32, F_HID / 32), dim3(32, 8)>>>(Y2, W2f, F_HID, F_OUT);
    // 3) cast x to fp16
    {
        int n4 = (N_TOK * F_IN) / 4;
        cast_f16<<<(n4 + 255) / 256, 256>>>((const float4*)x, (uint2*)x16, n4);
    }
    // 4) h = relu(x @ W1p^T + b1) -> fp16   (tile 128x128)
    gemm_f16<true><<<dim3(F_HID / 128, N_TOK / 128), 256, GEMM_SMEM>>>(
        x16, W1f, b1, nullptr, h16, F_HID, F_IN);
    // 5) out = h @ W2p^T + b2 -> fp32       (tile 128x128)
    gemm_f16<false><<<dim3(F_OUT / 128, N_TOK / 128), 256, GEMM_SMEM>>>(
        h16, W2f, b2, out, nullptr, F_OUT, F_HID);
}

// round 10
// speedup vs baseline: 1.2145x; 1.2055x over previous
#include <cuda_runtime.h>
#include <cuda_fp16.h>
#include <math.h>
#include <stdint.h>

#define N_TOK 32768
#define F_IN  512
#define F_HID 2048
#define F_OUT 512

// ---------------- scratch (static device globals; no runtime alloc) ----------
__device__ float g_lo1[F_IN],  g_cp1[F_IN],  g_rd1[F_IN];
__device__ float g_lo2[F_HID], g_cp2[F_HID], g_rd2[F_HID];
__device__ float g_Y1[F_IN * F_HID];               // solve(M1^T, W1^T): [512][2048]
__device__ float g_Y2[F_HID * F_OUT];              // [2048][512]
__device__ __half g_W1[F_HID * F_IN];              // folded W1 fp16 [2048][512]
__device__ __half g_W2[F_OUT * F_HID];             // folded W2 fp16 [512][2048]
__device__ __half g_x16[(size_t)N_TOK * F_IN];     // x fp16   32 MB
__device__ __half g_h16[(size_t)N_TOK * F_HID];    // h fp16  128 MB

// ======================= helpers =======================
__device__ __forceinline__ uint32_t smem_u32(const void* p) {
    uint32_t a;
    asm("{ .reg .u64 t; cvta.to.shared.u64 t, %1; cvt.u32.u64 %0, t; }"
        : "=r"(a) : "l"(p));
    return a;
}
__device__ __forceinline__ void cp16(uint32_t dst, const void* src) {
    asm volatile("cp.async.cg.shared.global [%0], [%1], 16;" :: "r"(dst), "l"(src));
}
__device__ __forceinline__ void cp_commit() {
    asm volatile("cp.async.commit_group;" ::: "memory");
}
template <int NN> __device__ __forceinline__ void cp_wait() {
    asm volatile("cp.async.wait_group %0;" :: "n"(NN) : "memory");
}
__device__ __forceinline__ void ldm_x4(uint32_t& r0, uint32_t& r1, uint32_t& r2,
                                       uint32_t& r3, uint32_t a) {
    asm volatile("ldmatrix.sync.aligned.m8n8.x4.shared.b16 {%0,%1,%2,%3}, [%4];"
        : "=r"(r0), "=r"(r1), "=r"(r2), "=r"(r3) : "r"(a));
}
__device__ __forceinline__ void mma_f16(float* c, const uint32_t* a,
                                        uint32_t b0, uint32_t b1) {
    asm volatile("mma.sync.aligned.m16n8k16.row.col.f32.f16.f16.f32 "
        "{%0,%1,%2,%3}, {%4,%5,%6,%7}, {%8,%9}, {%0,%1,%2,%3};"
        : "+f"(c[0]), "+f"(c[1]), "+f"(c[2]), "+f"(c[3])
        : "r"(a[0]), "r"(a[1]), "r"(a[2]), "r"(a[3]), "r"(b0), "r"(b1));
}
__device__ __forceinline__ uint32_t packh(__half a, __half b) {
    return (uint32_t)__half_as_ushort(a) | ((uint32_t)__half_as_ushort(b) << 16);
}

// ======================= prep kernels (R7 verbatim) =======================
__global__ void prep_both(const float* d1, const float* l1, const float* u1,
                          const float* d2, const float* l2, const float* u2,
                          float* lo1, float* cp1, float* rd1,
                          float* lo2, float* cp2, float* rd2) {
    __shared__ float sd[2048], slo[2048], sup[2048];
    const float *d, *l, *u; float *lo, *cp, *rd; int n;
    if (blockIdx.x == 0) { d = d1; l = l1; u = u1; lo = lo1; cp = cp1; rd = rd1; n = F_IN; }
    else                 { d = d2; l = l2; u = u2; lo = lo2; cp = cp2; rd = rd2; n = F_HID; }
    int t = threadIdx.x;
    for (int i = t; i < n; i += blockDim.x) {
        float di = d[i];
        float sp = (di > 20.f) ? di : log1pf(expf(di));
        sd[i]  = sp + 2.f;
        slo[i] = (i > 0)     ? tanhf(u[i - 1]) : 0.f;   // sub of M^T
        sup[i] = (i < n - 1) ? tanhf(l[i])     : 0.f;   // super of M^T
    }
    __syncthreads();
    if (t == 0) {
        float cprev = 0.f;
        for (int i = 0; i < n; i++) {
            float den = sd[i] - slo[i] * cprev;
            float r = 1.f / den;
            sd[i] = r;
            cprev = sup[i] * r;
            sup[i] = cprev;
        }
    }
    __syncthreads();
    for (int i = t; i < n; i += blockDim.x) {
        rd[i] = sd[i]; cp[i] = sup[i]; lo[i] = slo[i];
    }
}

__device__ __forceinline__ void solve_one(
    const float* __restrict__ lo, const float* __restrict__ cp,
    const float* __restrict__ rd, const float* __restrict__ r,
    int n, int nrhs, float* __restrict__ Y, int j) {
    float z = r[0] * rd[0];
    Y[j] = z;
#pragma unroll 4
    for (int i = 1; i < n; i++) {
        z = (r[i] - lo[i] * z) * rd[i];
        Y[(size_t)i * nrhs + j] = z;
    }
    float y = z;
#pragma unroll 4
    for (int i = n - 2; i >= 0; i--) {
        y = Y[(size_t)i * nrhs + j] - cp[i] * y;
        Y[(size_t)i * nrhs + j] = y;
    }
}

__global__ void solve_both(const float* lo1, const float* cp1, const float* rd1,
                           const float* W1, float* Y1,
                           const float* lo2, const float* cp2, const float* rd2,
                           const float* W2, float* Y2) {
    int bid = blockIdx.x, t = threadIdx.x;
    if (bid < 16) {
        int j = bid * 128 + t;
        solve_one(lo1, cp1, rd1, W1 + (size_t)j * F_IN, F_IN, F_HID, Y1, j);
    } else {
        int j = (bid - 16) * 128 + t;
        solve_one(lo2, cp2, rd2, W2 + (size_t)j * F_HID, F_HID, F_OUT, Y2, j);
    }
}

// transpose [R][C] fp32 -> [C][R] fp16
__global__ void trans_f16(const float* __restrict__ in, __half* __restrict__ out,
                          int R, int C) {
    __shared__ float t[32][33];
    int c0 = blockIdx.x * 32, r0 = blockIdx.y * 32;
    int x = threadIdx.x, y = threadIdx.y;
#pragma unroll
    for (int i = 0; i < 32; i += 8)
        t[y + i][x] = in[(size_t)(r0 + y + i) * C + c0 + x];
    __syncthreads();
#pragma unroll
    for (int i = 0; i < 32; i += 8)
        out[(size_t)(c0 + y + i) * R + r0 + x] = __float2half_rn(t[x][y + i]);
}

// cast x fp32 -> fp16
__global__ void cast_f16(const float4* __restrict__ x, uint2* __restrict__ o, int n4) {
    int i = blockIdx.x * blockDim.x + threadIdx.x;
    if (i >= n4) return;
    float4 v = x[i];
    o[i] = make_uint2(packh(__float2half_rn(v.x), __float2half_rn(v.y)),
                      packh(__float2half_rn(v.z), __float2half_rn(v.w)));
}

// ======================= fp16 mma.sync GEMM (BK=64) =======================
// C[M,N] = A[M,K] @ B[N,K]^T (+bias)(+relu). fp16 in, fp32 accum.
// CTA 128x128, 8 warps (32m x 64n warp tile), BK=64 per stage, double buffer.
// 64 HMMA/warp per sync-pair (2x R7's amortization), 64 KB smem, 2 CTAs/SM.
#define GSTAGES 2
#define TILE_A  16384u                  // 128x64 fp16 (128B rows)
#define STG_BYTES (2u * TILE_A)         // A + B = 32 KB / stage
#define GEMM_SMEM (GSTAGES * STG_BYTES) // 64 KB

// canonical SW128 swizzle for 128B rows: 16B-chunk c16 in 0..7
__device__ __forceinline__ uint32_t swz(int r, int c16) {
    return (uint32_t)(r * 128 + ((c16 ^ (r & 7)) << 4));
}

__device__ __forceinline__ void load_stage(uint32_t sbase, int buf,
    const __half* A, const __half* B,
    int rowB, int colB, int K, int off, int tid) {
    uint32_t s0 = sbase + (uint32_t)buf * STG_BYTES;
#pragma unroll
    for (int i = 0; i < 4; i++) {
        int flat = tid + i * 256;          // 0..1023
        int r = flat >> 3, c = flat & 7;
        uint32_t sw = swz(r, c);
        cp16(s0 + sw,          A + (size_t)(rowB + r) * K + off + c * 8);
        cp16(s0 + TILE_A + sw, B + (size_t)(colB + r) * K + off + c * 8);
    }
    cp_commit();
}

template <bool FUSE>   // FUSE: relu + fp16 out (Ch); else fp32 out (Cf)
__global__ void __launch_bounds__(256, 2) gemm_f16(
    const __half* __restrict__ A, const __half* __restrict__ B,
    const float* __restrict__ bias, float* __restrict__ Cf,
    __half* __restrict__ Ch, int N, int K) {
    extern __shared__ char smem[];
    uint32_t sb = smem_u32(smem);
    const int tid = threadIdx.x;
    const int lane = tid & 31, wid = tid >> 5;
    const int wm = wid & 3, wn = wid >> 2;       // warp tile 32(m) x 64(n)
    const int rowB = blockIdx.y * 128, colB = blockIdx.x * 128;
    const int per = K >> 6;                      // 64-K stages

    float acc[2][8][4] = {};

    // prologue: stage 0
    load_stage(sb, 0, A, B, rowB, colB, K, 0, tid);

    const int lr = lane & 15, kh = lane >> 4;
    const int lg = lane >> 2, lt = lane & 3;

    for (int s = 0; s < per; s++) {
        cp_wait<0>();
        __syncthreads();

        int pf = s + 1;
        if (pf < per)
            load_stage(sb, pf & 1, A, B, rowB, colB, K, pf << 6, tid);
        else
            cp_commit();

        uint32_t sA = sb + (uint32_t)(s & 1) * STG_BYTES;
        uint32_t sBs = sA + TILE_A;
#pragma unroll
        for (int kk = 0; kk < 4; kk++) {
            uint32_t a[2][4];
#pragma unroll
            for (int mt = 0; mt < 2; mt++) {
                int r = wm * 32 + mt * 16 + lr;
                ldm_x4(a[mt][0], a[mt][1], a[mt][2], a[mt][3],
                       sA + swz(r, 2 * kk + kh));
            }
#pragma unroll
            for (int pt = 0; pt < 4; pt++) {
                int r = wn * 64 + pt * 16 + lr;
                uint32_t b0, b1, b2, b3;
                ldm_x4(b0, b1, b2, b3, sBs + swz(r, 2 * kk + kh));
#pragma unroll
                for (int mt = 0; mt < 2; mt++) {
                    mma_f16(acc[mt][2 * pt],     a[mt], b0, b2);
                    mma_f16(acc[mt][2 * pt + 1], a[mt], b1, b3);
                }
            }
        }
        __syncthreads();
    }

    // epilogue
#pragma unroll
    for (int mt = 0; mt < 2; mt++) {
        int r0 = rowB + wm * 32 + mt * 16 + lg;
#pragma unroll
        for (int n8 = 0; n8 < 8; n8++) {
            int c = colB + wn * 64 + n8 * 8 + 2 * lt;
            float b0v = bias[c], b1v = bias[c + 1];
            float v0 = acc[mt][n8][0] + b0v;
            float v1 = acc[mt][n8][1] + b1v;
            float v2 = acc[mt][n8][2] + b0v;
            float v3 = acc[mt][n8][3] + b1v;
            if (FUSE) {
                v0 = fmaxf(v0, 0.f); v1 = fmaxf(v1, 0.f);
                v2 = fmaxf(v2, 0.f); v3 = fmaxf(v3, 0.f);
                *(uint32_t*)(Ch + (size_t)r0 * N + c) =
                    packh(__float2half_rn(v0), __float2half_rn(v1));
                *(uint32_t*)(Ch + (size_t)(r0 + 8) * N + c) =
                    packh(__float2half_rn(v2), __float2half_rn(v3));
            } else {
                *(float2*)(Cf + (size_t)r0 * N + c)       = make_float2(v0, v1);
                *(float2*)(Cf + (size_t)(r0 + 8) * N + c) = make_float2(v2, v3);
            }
        }
    }
}

// ======================= launch =======================
extern "C" void kernel_launch(void* const* d_in, const int* in_sizes, int n_in,
                              void* d_out, int out_size) {
    const float* x  = (const float*)d_in[0];
    const float* d1 = (const float*)d_in[1];
    const float* l1 = (const float*)d_in[2];
    const float* u1 = (const float*)d_in[3];
    const float* W1 = (const float*)d_in[4];
    const float* b1 = (const float*)d_in[5];
    const float* d2 = (const float*)d_in[6];
    const float* l2 = (const float*)d_in[7];
    const float* u2 = (const float*)d_in[8];
    const float* W2 = (const float*)d_in[9];
    const float* b2 = (const float*)d_in[10];
    float* out = (float*)d_out;

    float *lo1, *cp1, *rd1, *lo2, *cp2, *rd2, *Y1, *Y2;
    __half *W1f, *W2f, *x16, *h16;
    cudaGetSymbolAddress((void**)&lo1, g_lo1);
    cudaGetSymbolAddress((void**)&cp1, g_cp1);
    cudaGetSymbolAddress((void**)&rd1, g_rd1);
    cudaGetSymbolAddress((void**)&lo2, g_lo2);
    cudaGetSymbolAddress((void**)&cp2, g_cp2);
    cudaGetSymbolAddress((void**)&rd2, g_rd2);
    cudaGetSymbolAddress((void**)&Y1,  g_Y1);
    cudaGetSymbolAddress((void**)&Y2,  g_Y2);
    cudaGetSymbolAddress((void**)&W1f, g_W1);
    cudaGetSymbolAddress((void**)&W2f, g_W2);
    cudaGetSymbolAddress((void**)&x16, g_x16);
    cudaGetSymbolAddress((void**)&h16, g_h16);

    cudaFuncSetAttribute(gemm_f16<true>,
                         cudaFuncAttributeMaxDynamicSharedMemorySize, GEMM_SMEM);
    cudaFuncSetAttribute(gemm_f16<false>,
                         cudaFuncAttributeMaxDynamicSharedMemorySize, GEMM_SMEM);

    // 1) factorize M1^T, M2^T
    prep_both<<<2, 256>>>(d1, l1, u1, d2, l2, u2, lo1, cp1, rd1, lo2, cp2, rd2);
    // 2) fold tridiag solves into weights: Y = solve(M^T, W^T)
    solve_both<<<20, 128>>>(lo1, cp1, rd1, W1, Y1, lo2, cp2, rd2, W2, Y2);
    // 3) transpose folded weights to row-major fp16
    trans_f16<<<dim3(F_HID / 32, F_IN / 32),  dim3(32, 8)>>>(Y1, W1f, F_IN,  F_HID);
    trans_f16<<<dim3(F_OUT / 32, F_HID / 32), dim3(32, 8)>>>(Y2, W2f, F_HID, F_OUT);
    // 4) cast x to fp16
    {
        int n4 = (N_TOK * F_IN) / 4;
        cast_f16<<<(n4 + 255) / 256, 256>>>((const float4*)x, (uint2*)x16, n4);
    }
    // 5) h = relu(x @ W1p^T + b1) -> fp16   (tile 128x128)
    gemm_f16<true><<<dim3(F_HID / 128, N_TOK / 128), 256, GEMM_SMEM>>>(
        x16, W1f, b1, nullptr, h16, F_HID, F_IN);
    // 6) out = h @ W2p^T + b2 -> fp32       (tile 128x128)
    gemm_f16<false><<<dim3(F_OUT / 128, N_TOK / 128), 256, GEMM_SMEM>>>(
        h16, W2f, b2, out, nullptr, F_OUT, F_HID);
}

// round 11
// speedup vs baseline: 1.2299x; 1.0127x over previous
#include <cuda_runtime.h>
#include <cuda_fp16.h>
#include <math.h>
#include <stdint.h>

#define N_TOK 32768
#define F_IN  512
#define F_HID 2048
#define F_OUT 512

// ---------------- scratch (static device globals; no runtime alloc) ----------
__device__ float g_lo1[F_IN],  g_cp1[F_IN],  g_rd1[F_IN];
__device__ float g_lo2[F_HID], g_cp2[F_HID], g_rd2[F_HID];
__device__ float g_Y1[F_IN * F_HID];               // solve(M1^T, W1^T): [512][2048]
__device__ float g_Y2[F_HID * F_OUT];              // [2048][512]
__device__ __half g_W1[F_HID * F_IN];              // folded W1 fp16 [2048][512]
__device__ __half g_W2[F_OUT * F_HID];             // folded W2 fp16 [512][2048]
__device__ __half g_x16[(size_t)N_TOK * F_IN];     // x fp16   32 MB
__device__ __half g_h16[(size_t)N_TOK * F_HID];    // h fp16  128 MB

// ======================= helpers =======================
__device__ __forceinline__ uint32_t smem_u32(const void* p) {
    uint32_t a;
    asm("{ .reg .u64 t; cvta.to.shared.u64 t, %1; cvt.u32.u64 %0, t; }"
        : "=r"(a) : "l"(p));
    return a;
}
__device__ __forceinline__ void cp16(uint32_t dst, const void* src) {
    asm volatile("cp.async.cg.shared.global [%0], [%1], 16;" :: "r"(dst), "l"(src));
}
__device__ __forceinline__ void cp_commit() {
    asm volatile("cp.async.commit_group;" ::: "memory");
}
template <int NN> __device__ __forceinline__ void cp_wait() {
    asm volatile("cp.async.wait_group %0;" :: "n"(NN) : "memory");
}
__device__ __forceinline__ void ldm_x4(uint32_t& r0, uint32_t& r1, uint32_t& r2,
                                       uint32_t& r3, uint32_t a) {
    asm volatile("ldmatrix.sync.aligned.m8n8.x4.shared.b16 {%0,%1,%2,%3}, [%4];"
        : "=r"(r0), "=r"(r1), "=r"(r2), "=r"(r3) : "r"(a));
}
__device__ __forceinline__ void mma_f16(float* c, const uint32_t* a,
                                        uint32_t b0, uint32_t b1) {
    asm volatile("mma.sync.aligned.m16n8k16.row.col.f32.f16.f16.f32 "
        "{%0,%1,%2,%3}, {%4,%5,%6,%7}, {%8,%9}, {%0,%1,%2,%3};"
        : "+f"(c[0]), "+f"(c[1]), "+f"(c[2]), "+f"(c[3])
        : "r"(a[0]), "r"(a[1]), "r"(a[2]), "r"(a[3]), "r"(b0), "r"(b1));
}
__device__ __forceinline__ uint32_t packh(__half a, __half b) {
    return (uint32_t)__half_as_ushort(a) | ((uint32_t)__half_as_ushort(b) << 16);
}

// ======================= prep kernels (R7 verbatim) =======================
__global__ void prep_both(const float* d1, const float* l1, const float* u1,
                          const float* d2, const float* l2, const float* u2,
                          float* lo1, float* cp1, float* rd1,
                          float* lo2, float* cp2, float* rd2) {
    __shared__ float sd[2048], slo[2048], sup[2048];
    const float *d, *l, *u; float *lo, *cp, *rd; int n;
    if (blockIdx.x == 0) { d = d1; l = l1; u = u1; lo = lo1; cp = cp1; rd = rd1; n = F_IN; }
    else                 { d = d2; l = l2; u = u2; lo = lo2; cp = cp2; rd = rd2; n = F_HID; }
    int t = threadIdx.x;
    for (int i = t; i < n; i += blockDim.x) {
        float di = d[i];
        float sp = (di > 20.f) ? di : log1pf(expf(di));
        sd[i]  = sp + 2.f;
        slo[i] = (i > 0)     ? tanhf(u[i - 1]) : 0.f;   // sub of M^T
        sup[i] = (i < n - 1) ? tanhf(l[i])     : 0.f;   // super of M^T
    }
    __syncthreads();
    if (t == 0) {
        float cprev = 0.f;
        for (int i = 0; i < n; i++) {
            float den = sd[i] - slo[i] * cprev;
            float r = 1.f / den;
            sd[i] = r;
            cprev = sup[i] * r;
            sup[i] = cprev;
        }
    }
    __syncthreads();
    for (int i = t; i < n; i += blockDim.x) {
        rd[i] = sd[i]; cp[i] = sup[i]; lo[i] = slo[i];
    }
}

__device__ __forceinline__ void solve_one(
    const float* __restrict__ lo, const float* __restrict__ cp,
    const float* __restrict__ rd, const float* __restrict__ r,
    int n, int nrhs, float* __restrict__ Y, int j) {
    float z = r[0] * rd[0];
    Y[j] = z;
#pragma unroll 4
    for (int i = 1; i < n; i++) {
        z = (r[i] - lo[i] * z) * rd[i];
        Y[(size_t)i * nrhs + j] = z;
    }
    float y = z;
#pragma unroll 4
    for (int i = n - 2; i >= 0; i--) {
        y = Y[(size_t)i * nrhs + j] - cp[i] * y;
        Y[(size_t)i * nrhs + j] = y;
    }
}

__global__ void solve_both(const float* lo1, const float* cp1, const float* rd1,
                           const float* W1, float* Y1,
                           const float* lo2, const float* cp2, const float* rd2,
                           const float* W2, float* Y2) {
    int bid = blockIdx.x, t = threadIdx.x;
    if (bid < 16) {
        int j = bid * 128 + t;
        solve_one(lo1, cp1, rd1, W1 + (size_t)j * F_IN, F_IN, F_HID, Y1, j);
    } else {
        int j = (bid - 16) * 128 + t;
        solve_one(lo2, cp2, rd2, W2 + (size_t)j * F_HID, F_HID, F_OUT, Y2, j);
    }
}

// transpose [R][C] fp32 -> [C][R] fp16
__global__ void trans_f16(const float* __restrict__ in, __half* __restrict__ out,
                          int R, int C) {
    __shared__ float t[32][33];
    int c0 = blockIdx.x * 32, r0 = blockIdx.y * 32;
    int x = threadIdx.x, y = threadIdx.y;
#pragma unroll
    for (int i = 0; i < 32; i += 8)
        t[y + i][x] = in[(size_t)(r0 + y + i) * C + c0 + x];
    __syncthreads();
#pragma unroll
    for (int i = 0; i < 32; i += 8)
        out[(size_t)(c0 + y + i) * R + r0 + x] = __float2half_rn(t[x][y + i]);
}

// cast x fp32 -> fp16
__global__ void cast_f16(const float4* __restrict__ x, uint2* __restrict__ o, int n4) {
    int i = blockIdx.x * blockDim.x + threadIdx.x;
    if (i >= n4) return;
    float4 v = x[i];
    o[i] = make_uint2(packh(__float2half_rn(v.x), __float2half_rn(v.y)),
                      packh(__float2half_rn(v.z), __float2half_rn(v.w)));
}

// ======================= fp16 mma.sync GEMM (BK=64, frag-pipelined) ========
// C[M,N] = A[M,K] @ B[N,K]^T (+bias)(+relu). fp16 in, fp32 accum.
// CTA 128x128, 8 warps (32m x 64n warp tile), BK=64 per stage, double buffer.
// Fragments software-pipelined: every ldmatrix issues >=4 MMAs before its use.
#define GSTAGES 2
#define TILE_A  16384u                  // 128x64 fp16 (128B rows)
#define STG_BYTES (2u * TILE_A)         // A + B = 32 KB / stage
#define GEMM_SMEM (GSTAGES * STG_BYTES) // 64 KB

// canonical SW128 swizzle for 128B rows: 16B-chunk c16 in 0..7
__device__ __forceinline__ uint32_t swz(int r, int c16) {
    return (uint32_t)(r * 128 + ((c16 ^ (r & 7)) << 4));
}

__device__ __forceinline__ void load_stage(uint32_t sbase, int buf,
    const __half* A, const __half* B,
    int rowB, int colB, int K, int off, int tid) {
    uint32_t s0 = sbase + (uint32_t)buf * STG_BYTES;
#pragma unroll
    for (int i = 0; i < 4; i++) {
        int flat = tid + i * 256;          // 0..1023
        int r = flat >> 3, c = flat & 7;
        uint32_t sw = swz(r, c);
        cp16(s0 + sw,          A + (size_t)(rowB + r) * K + off + c * 8);
        cp16(s0 + TILE_A + sw, B + (size_t)(colB + r) * K + off + c * 8);
    }
    cp_commit();
}

template <bool FUSE>   // FUSE: relu + fp16 out (Ch); else fp32 out (Cf)
__global__ void __launch_bounds__(256, 2) gemm_f16(
    const __half* __restrict__ A, const __half* __restrict__ B,
    const float* __restrict__ bias, float* __restrict__ Cf,
    __half* __restrict__ Ch, int N, int K) {
    extern __shared__ char smem[];
    uint32_t sb = smem_u32(smem);
    const int tid = threadIdx.x;
    const int lane = tid & 31, wid = tid >> 5;
    const int wm = wid & 3, wn = wid >> 2;       // warp tile 32(m) x 64(n)
    const int rowB = blockIdx.y * 128, colB = blockIdx.x * 128;
    const int per = K >> 6;                      // 64-K stages

    float acc[2][8][4] = {};

    // prologue: stage 0
    load_stage(sb, 0, A, B, rowB, colB, K, 0, tid);

    const int lr = lane & 15, kh = lane >> 4;
    const int lg = lane >> 2, lt = lane & 3;
    const int rA0 = wm * 32 + lr, rA1 = wm * 32 + 16 + lr;
    const int rB0 = wn * 64 + lr;

    for (int s = 0; s < per; s++) {
        cp_wait<0>();
        __syncthreads();

        int pf = s + 1;
        if (pf < per)
            load_stage(sb, pf & 1, A, B, rowB, colB, K, pf << 6, tid);
        else
            cp_commit();

        uint32_t sA = sb + (uint32_t)(s & 1) * STG_BYTES;
        uint32_t sBs = sA + TILE_A;

        // fragment double buffers
        uint32_t afr[2][2][4];     // [buf][mt][reg]
        uint32_t bfr[2][4];        // [buf][reg]

        // preload kk=0 A fragments + first B fragment
        ldm_x4(afr[0][0][0], afr[0][0][1], afr[0][0][2], afr[0][0][3],
               sA + swz(rA0, kh));
        ldm_x4(afr[0][1][0], afr[0][1][1], afr[0][1][2], afr[0][1][3],
               sA + swz(rA1, kh));
        ldm_x4(bfr[0][0], bfr[0][1], bfr[0][2], bfr[0][3],
               sBs + swz(rB0, kh));

#pragma unroll
        for (int kk = 0; kk < 4; kk++) {
            const int ca = kk & 1;
            // prefetch A fragments for kk+1 (land during this kk's 16 MMAs)
            if (kk < 3) {
                ldm_x4(afr[ca ^ 1][0][0], afr[ca ^ 1][0][1],
                       afr[ca ^ 1][0][2], afr[ca ^ 1][0][3],
                       sA + swz(rA0, 2 * (kk + 1) + kh));
                ldm_x4(afr[ca ^ 1][1][0], afr[ca ^ 1][1][1],
                       afr[ca ^ 1][1][2], afr[ca ^ 1][1][3],
                       sA + swz(rA1, 2 * (kk + 1) + kh));
            }
#pragma unroll
            for (int pt = 0; pt < 4; pt++) {
                const int cb = (kk * 4 + pt) & 1;
                // prefetch next B fragment before consuming current one
                if (pt < 3)
                    ldm_x4(bfr[cb ^ 1][0], bfr[cb ^ 1][1],
                           bfr[cb ^ 1][2], bfr[cb ^ 1][3],
                           sBs + swz(rB0 + (pt + 1) * 16, 2 * kk + kh));
                else if (kk < 3)
                    ldm_x4(bfr[cb ^ 1][0], bfr[cb ^ 1][1],
                           bfr[cb ^ 1][2], bfr[cb ^ 1][3],
                           sBs + swz(rB0, 2 * (kk + 1) + kh));
#pragma unroll
                for (int mt = 0; mt < 2; mt++) {
                    mma_f16(acc[mt][2 * pt],     afr[ca][mt], bfr[cb][0], bfr[cb][2]);
                    mma_f16(acc[mt][2 * pt + 1], afr[ca][mt], bfr[cb][1], bfr[cb][3]);
                }
            }
        }
        __syncthreads();
    }

    // epilogue
#pragma unroll
    for (int mt = 0; mt < 2; mt++) {
        int r0 = rowB + wm * 32 + mt * 16 + lg;
#pragma unroll
        for (int n8 = 0; n8 < 8; n8++) {
            int c = colB + wn * 64 + n8 * 8 + 2 * lt;
            float b0v = bias[c], b1v = bias[c + 1];
            float v0 = acc[mt][n8][0] + b0v;
            float v1 = acc[mt][n8][1] + b1v;
            float v2 = acc[mt][n8][2] + b0v;
            float v3 = acc[mt][n8][3] + b1v;
            if (FUSE) {
                v0 = fmaxf(v0, 0.f); v1 = fmaxf(v1, 0.f);
                v2 = fmaxf(v2, 0.f); v3 = fmaxf(v3, 0.f);
                *(uint32_t*)(Ch + (size_t)r0 * N + c) =
                    packh(__float2half_rn(v0), __float2half_rn(v1));
                *(uint32_t*)(Ch + (size_t)(r0 + 8) * N + c) =
                    packh(__float2half_rn(v2), __float2half_rn(v3));
            } else {
                *(float2*)(Cf + (size_t)r0 * N + c)       = make_float2(v0, v1);
                *(float2*)(Cf + (size_t)(r0 + 8) * N + c) = make_float2(v2, v3);
            }
        }
    }
}

// ======================= launch =======================
extern "C" void kernel_launch(void* const* d_in, const int* in_sizes, int n_in,
                              void* d_out, int out_size) {
    const float* x  = (const float*)d_in[0];
    const float* d1 = (const float*)d_in[1];
    const float* l1 = (const float*)d_in[2];
    const float* u1 = (const float*)d_in[3];
    const float* W1 = (const float*)d_in[4];
    const float* b1 = (const float*)d_in[5];
    const float* d2 = (const float*)d_in[6];
    const float* l2 = (const float*)d_in[7];
    const float* u2 = (const float*)d_in[8];
    const float* W2 = (const float*)d_in[9];
    const float* b2 = (const float*)d_in[10];
    float* out = (float*)d_out;

    float *lo1, *cp1, *rd1, *lo2, *cp2, *rd2, *Y1, *Y2;
    __half *W1f, *W2f, *x16, *h16;
    cudaGetSymbolAddress((void**)&lo1, g_lo1);
    cudaGetSymbolAddress((void**)&cp1, g_cp1);
    cudaGetSymbolAddress((void**)&rd1, g_rd1);
    cudaGetSymbolAddress((void**)&lo2, g_lo2);
    cudaGetSymbolAddress((void**)&cp2, g_cp2);
    cudaGetSymbolAddress((void**)&rd2, g_rd2);
    cudaGetSymbolAddress((void**)&Y1,  g_Y1);
    cudaGetSymbolAddress((void**)&Y2,  g_Y2);
    cudaGetSymbolAddress((void**)&W1f, g_W1);
    cudaGetSymbolAddress((void**)&W2f, g_W2);
    cudaGetSymbolAddress((void**)&x16, g_x16);
    cudaGetSymbolAddress((void**)&h16, g_h16);

    cudaFuncSetAttribute(gemm_f16<true>,
                         cudaFuncAttributeMaxDynamicSharedMemorySize, GEMM_SMEM);
    cudaFuncSetAttribute(gemm_f16<false>,
                         cudaFuncAttributeMaxDynamicSharedMemorySize, GEMM_SMEM);

    // 1) factorize M1^T, M2^T
    prep_both<<<2, 256>>>(d1, l1, u1, d2, l2, u2, lo1, cp1, rd1, lo2, cp2, rd2);
    // 2) fold tridiag solves into weights: Y = solve(M^T, W^T)
    solve_both<<<20, 128>>>(lo1, cp1, rd1, W1, Y1, lo2, cp2, rd2, W2, Y2);
    // 3) transpose folded weights to row-major fp16
    trans_f16<<<dim3(F_HID / 32, F_IN / 32),  dim3(32, 8)>>>(Y1, W1f, F_IN,  F_HID);
    trans_f16<<<dim3(F_OUT / 32, F_HID / 32), dim3(32, 8)>>>(Y2, W2f, F_HID, F_OUT);
    // 4) cast x to fp16
    {
        int n4 = (N_TOK * F_IN) / 4;
        cast_f16<<<(n4 + 255) / 256, 256>>>((const float4*)x, (uint2*)x16, n4);
    }
    // 5) h = relu(x @ W1p^T + b1) -> fp16   (tile 128x128)
    gemm_f16<true><<<dim3(F_HID / 128, N_TOK / 128), 256, GEMM_SMEM>>>(
        x16, W1f, b1, nullptr, h16, F_HID, F_IN);
    // 6) out = h @ W2p^T + b2 -> fp32       (tile 128x128)
    gemm_f16<false><<<dim3(F_OUT / 128, N_TOK / 128), 256, GEMM_SMEM>>>(
        h16, W2f, b2, out, nullptr, F_OUT, F_HID);
}